// round 3
// baseline (speedup 1.0000x reference)
#include <cuda_runtime.h>
#include <math.h>

#define NN 16384
#define NE 65536

// ---------------- scratch (static __device__, aligned for LDG/STG.128) ----
static __device__ __align__(256) float g_U[128 * 128];
static __device__ __align__(256) float g_V[128 * 128];
static __device__ __align__(256) float g_acc[10][NN * 128];   // 0:a 1..3:b 4..9: m(xx,yy,zz,xy,xz,yz)
static __device__ __align__(256) float g_T[NN * 128];         // layernormed tensor norm
static __device__ __align__(256) float g_H1[NN * 256];
static __device__ __align__(256) float g_NR[NN * 384];        // nrm, [n][h*3+c]
static __device__ __align__(256) float g_mix[10][NN * 128];   // channel-mixed comps
static __device__ __align__(256) float g_X[NN * 384];
static __device__ __align__(256) float g_XN[NN * 384];
static __device__ __align__(256) float g_G1[NN * 128];
static __device__ __align__(256) float g_G2[NN * 64];

// ---------------- constants ----------------
__device__ __forceinline__ float silu(float x) { return x / (1.f + expf(-x)); }

// exp(-4.5)
#define RBF_START 0.011108996538242306
#define RBF_BETA  (1.0 / ((0.0625 * (1.0 - RBF_START)) * (0.0625 * (1.0 - RBF_START))))
#define RBF_ALPHA (5.0 / 4.5)
#define PI_OVER_C 0.6981317007977318   // pi / 4.5

// ---------------- zero accumulators ----------------
__global__ void k_zero() {
    size_t i = (size_t)blockIdx.x * blockDim.x + threadIdx.x;
    float4* p = (float4*)&g_acc[0][0];
    size_t n4 = (size_t)10 * NN * 128 / 4;
    if (i < n4) p[i] = make_float4(0.f, 0.f, 0.f, 0.f);
}

// ---------------- U/V lookup tables (Z embedding folded GEMM) ----------------
__global__ void k_prep(const float* __restrict__ emb_w,
                       const float* __restrict__ emb2_w,
                       const float* __restrict__ emb2_b) {
    int zt = blockIdx.x;   // 0..127
    int h  = threadIdx.x;  // 0..127
    float u = emb2_b[h];
    float v = 0.f;
    #pragma unroll 4
    for (int k = 0; k < 128; k++) {
        float e = emb_w[zt * 128 + k];
        u = fmaf(e, emb2_w[h * 256 + k], u);
        v = fmaf(e, emb2_w[h * 256 + 128 + k], v);
    }
    g_U[zt * 128 + h] = u;
    g_V[zt * 128 + h] = v;
}

// ---------------- edge scatter: one block (128 thr = channels) per edge ----------------
// NOTE: edge_index arrives as int32 (JAX x64 disabled downcasts jnp.int64).
__global__ void k_edge(const int* __restrict__ ei,
                       const float* __restrict__ pos,
                       const int* __restrict__ z,
                       const float* __restrict__ dp1w, const float* __restrict__ dp1b,
                       const float* __restrict__ dp2w, const float* __restrict__ dp2b,
                       const float* __restrict__ dp3w, const float* __restrict__ dp3b) {
    int e = blockIdx.x;
    int h = threadIdx.x;
    int src = ei[e];
    int dst = ei[NE + e];
    float vx = pos[src * 3 + 0] - pos[dst * 3 + 0];
    float vy = pos[src * 3 + 1] - pos[dst * 3 + 1];
    float vz = pos[src * 3 + 2] - pos[dst * 3 + 2];
    float d = sqrtf(vx * vx + vy * vy + vz * vz);
    bool selfe = (src == dst);
    if (!selfe && !(d < 4.5f)) return;  // cutoff == 0 => edge contributes exactly 0

    float cut = 0.5f * (cosf(d * (float)PI_OVER_C) + 1.0f);
    float inv = selfe ? 1.0f : (1.0f / d);
    vx *= inv; vy *= inv; vz *= inv;

    __shared__ __align__(16) float s_attr[32];
    if (h < 32) {
        float mean = (float)RBF_START + (float)h * (float)((1.0 - RBF_START) / 31.0);
        float g = expf(-(float)RBF_ALPHA * d);
        float diff = g - mean;
        s_attr[h] = cut * expf(-(float)RBF_BETA * diff * diff);
    }
    __syncthreads();

    float Z = g_U[(z[src] << 7) + h] + g_V[(z[dst] << 7) + h];
    float C = cut * Z;

    float d1 = dp1b[h], d2 = dp2b[h], d3 = dp3b[h];
    #pragma unroll
    for (int r = 0; r < 32; r += 4) {
        float4 a4 = *(const float4*)&s_attr[r];
        float4 w1 = *(const float4*)&dp1w[h * 32 + r];
        float4 w2 = *(const float4*)&dp2w[h * 32 + r];
        float4 w3 = *(const float4*)&dp3w[h * 32 + r];
        d1 += a4.x * w1.x + a4.y * w1.y + a4.z * w1.z + a4.w * w1.w;
        d2 += a4.x * w2.x + a4.y * w2.y + a4.z * w2.z + a4.w * w2.w;
        d3 += a4.x * w3.x + a4.y * w3.y + a4.z * w3.z + a4.w * w3.w;
    }
    float a  = d1 * C;
    float cb = d2 * C;
    float cs = d3 * C;
    int i = (src << 7) + h;
    atomicAdd(&g_acc[0][i], a);
    atomicAdd(&g_acc[1][i], cb * vx);
    atomicAdd(&g_acc[2][i], cb * vy);
    atomicAdd(&g_acc[3][i], cb * vz);
    atomicAdd(&g_acc[4][i], cs * vx * vx);
    atomicAdd(&g_acc[5][i], cs * vy * vy);
    atomicAdd(&g_acc[6][i], cs * vz * vz);
    atomicAdd(&g_acc[7][i], cs * vx * vy);
    atomicAdd(&g_acc[8][i], cs * vx * vz);
    atomicAdd(&g_acc[9][i], cs * vy * vz);
}

// ---------------- tensor norm + layernorm(128) ----------------
__global__ void k_tnorm(const float* __restrict__ gam, const float* __restrict__ bet) {
    int n = blockIdx.x, h = threadIdx.x;
    int i = (n << 7) + h;
    float a  = g_acc[0][i];
    float bx = g_acc[1][i], by = g_acc[2][i], bz = g_acc[3][i];
    float xx = g_acc[4][i], yy = g_acc[5][i], zz = g_acc[6][i];
    float xy = g_acc[7][i], xz = g_acc[8][i], yz = g_acc[9][i];
    float tr = xx + yy + zz;
    float ms = xx * xx + yy * yy + zz * zz + 2.f * (xy * xy + xz * xz + yz * yz);
    float tn = 3.f * a * a + 2.f * (bx * bx + by * by + bz * bz) + ms - tr * tr * (1.f / 3.f);

    __shared__ float red[4];
    float v = tn;
    #pragma unroll
    for (int o = 16; o; o >>= 1) v += __shfl_xor_sync(0xffffffffu, v, o);
    if ((h & 31) == 0) red[h >> 5] = v;
    __syncthreads();
    float mean = (red[0] + red[1] + red[2] + red[3]) * (1.f / 128.f);
    __syncthreads();
    float dev = tn - mean;
    v = dev * dev;
    #pragma unroll
    for (int o = 16; o; o >>= 1) v += __shfl_xor_sync(0xffffffffu, v, o);
    if ((h & 31) == 0) red[h >> 5] = v;
    __syncthreads();
    float var = (red[0] + red[1] + red[2] + red[3]) * (1.f / 128.f);
    g_T[i] = dev * rsqrtf(var + 1e-5f) * gam[h] + bet[h];
}

// ---------------- generic SIMT SGEMM: C[M,F] = A[M,K] @ W[F,K]^T (+bias)(+silu) ----
// BM=128, BN=64, BK=8, thread tile 8x4, 256 threads
__device__ __forceinline__ void sgemm_body(const float* __restrict__ A,
                                           const float* __restrict__ W,
                                           const float* __restrict__ bias,
                                           float* __restrict__ C,
                                           int K, int F, bool act) {
    __shared__ __align__(16) float As[8][128];
    __shared__ __align__(16) float Ws[8][64];
    const int tid = threadIdx.x;
    const int tx = tid & 15, ty = tid >> 4;
    const int m0 = blockIdx.x << 7;
    const int f0 = blockIdx.y << 6;
    float acc[8][4];
    #pragma unroll
    for (int i = 0; i < 8; i++)
        #pragma unroll
        for (int j = 0; j < 4; j++) acc[i][j] = 0.f;

    const int arow = tid >> 1, acol = (tid & 1) << 2;
    const int wrow = (tid & 127) >> 1, wcol = acol;
    const float* Ag = A + (size_t)(m0 + arow) * K + acol;
    const float* Wg = W + (size_t)(f0 + wrow) * K + wcol;

    for (int k0 = 0; k0 < K; k0 += 8) {
        float4 av = *(const float4*)(Ag + k0);
        As[acol + 0][arow] = av.x; As[acol + 1][arow] = av.y;
        As[acol + 2][arow] = av.z; As[acol + 3][arow] = av.w;
        if (tid < 128) {
            float4 wv = *(const float4*)(Wg + k0);
            Ws[wcol + 0][wrow] = wv.x; Ws[wcol + 1][wrow] = wv.y;
            Ws[wcol + 2][wrow] = wv.z; Ws[wcol + 3][wrow] = wv.w;
        }
        __syncthreads();
        #pragma unroll
        for (int k = 0; k < 8; k++) {
            float4 a0 = *(const float4*)&As[k][ty << 3];
            float4 a1 = *(const float4*)&As[k][(ty << 3) + 4];
            float4 wv = *(const float4*)&Ws[k][tx << 2];
            float am[8] = {a0.x, a0.y, a0.z, a0.w, a1.x, a1.y, a1.z, a1.w};
            float wn[4] = {wv.x, wv.y, wv.z, wv.w};
            #pragma unroll
            for (int i = 0; i < 8; i++)
                #pragma unroll
                for (int j = 0; j < 4; j++)
                    acc[i][j] = fmaf(am[i], wn[j], acc[i][j]);
        }
        __syncthreads();
    }

    float bj[4];
    #pragma unroll
    for (int j = 0; j < 4; j++) bj[j] = bias ? bias[f0 + (tx << 2) + j] : 0.f;
    #pragma unroll
    for (int i = 0; i < 8; i++) {
        float v0 = acc[i][0] + bj[0];
        float v1 = acc[i][1] + bj[1];
        float v2 = acc[i][2] + bj[2];
        float v3 = acc[i][3] + bj[3];
        if (act) { v0 = silu(v0); v1 = silu(v1); v2 = silu(v2); v3 = silu(v3); }
        *(float4*)&C[(size_t)(m0 + (ty << 3) + i) * F + f0 + (tx << 2)] =
            make_float4(v0, v1, v2, v3);
    }
}

__global__ void gemm_ls0(const float* W, const float* b)  { sgemm_body(g_T,       W, b,       g_H1,     128, 256, true);  }
__global__ void gemm_ls1(const float* W, const float* b)  { sgemm_body(g_H1,      W, b,       g_NR,     256, 384, true);  }
__global__ void gemm_mixI(const float* W)                 { sgemm_body(g_acc[0],  W, nullptr, g_mix[0], 128, 128, false); }
__global__ void gemm_mixB(const float* W)                 { sgemm_body(g_acc[1],  W, nullptr, g_mix[1], 128, 128, false); }
__global__ void gemm_mixS(const float* W)                 { sgemm_body(g_acc[4],  W, nullptr, g_mix[4], 128, 128, false); }
__global__ void gemm_lin(const float* W, const float* b)  { sgemm_body(g_XN,      W, b,       g_G1,     384, 128, true);  }
__global__ void gemm_ol1(const float* W, const float* b)  { sgemm_body(g_G1,      W, b,       g_G2,     128, 64,  true);  }

// ---------------- combine mixed comps into x[N,384] ----------------
__global__ void k_combine() {
    int idx = blockIdx.x * 256 + threadIdx.x;
    if (idx >= NN * 128) return;
    int n = idx >> 7, k = idx & 127;
    float Ip = g_mix[0][idx];
    float B0 = g_mix[1][idx], B1 = g_mix[2][idx], B2 = g_mix[3][idx];
    float xx = g_mix[4][idx], yy = g_mix[5][idx], zz = g_mix[6][idx];
    float xy = g_mix[7][idx], xz = g_mix[8][idx], yz = g_mix[9][idx];
    const float* nr = &g_NR[n * 384 + 3 * k];
    float n0 = nr[0], n1 = nr[1], n2 = nr[2];
    float t  = Ip * n0;
    float x0 = 3.f * t * t;
    float bb = B0 * B0 + B1 * B1 + B2 * B2;
    float x1 = 2.f * bb * n1 * n1;
    float tr = xx + yy + zz;
    float ms = xx * xx + yy * yy + zz * zz + 2.f * (xy * xy + xz * xz + yz * yz);
    float x2 = (ms - tr * tr * (1.f / 3.f)) * n2 * n2;
    g_X[n * 384 + k]       = x0;
    g_X[n * 384 + 128 + k] = x1;
    g_X[n * 384 + 256 + k] = x2;
}

// ---------------- layernorm over 384 ----------------
__global__ void k_ln384(const float* __restrict__ gam, const float* __restrict__ bet) {
    int n = blockIdx.x, j = threadIdx.x;
    float x = g_X[n * 384 + j];
    __shared__ float red[12];
    float v = x;
    #pragma unroll
    for (int o = 16; o; o >>= 1) v += __shfl_xor_sync(0xffffffffu, v, o);
    if ((j & 31) == 0) red[j >> 5] = v;
    __syncthreads();
    float s = 0.f;
    #pragma unroll
    for (int w = 0; w < 12; w++) s += red[w];
    float mean = s * (1.f / 384.f);
    __syncthreads();
    float dev = x - mean;
    v = dev * dev;
    #pragma unroll
    for (int o = 16; o; o >>= 1) v += __shfl_xor_sync(0xffffffffu, v, o);
    if ((j & 31) == 0) red[j >> 5] = v;
    __syncthreads();
    s = 0.f;
    #pragma unroll
    for (int w = 0; w < 12; w++) s += red[w];
    float var = s * (1.f / 384.f);
    g_XN[n * 384 + j] = dev * rsqrtf(var + 1e-5f) * gam[j] + bet[j];
}

// ---------------- final: y[n] = G2[n,:64] . ol2_w + b ----------------
__global__ void k_final(const float* __restrict__ w, const float* __restrict__ b,
                        float* __restrict__ y) {
    int gi = blockIdx.x * 256 + threadIdx.x;
    int n = gi >> 5, lane = gi & 31;
    if (n >= NN) return;
    float s = g_G2[n * 64 + lane] * w[lane] + g_G2[n * 64 + 32 + lane] * w[32 + lane];
    #pragma unroll
    for (int o = 16; o; o >>= 1) s += __shfl_xor_sync(0xffffffffu, s, o);
    if (lane == 0) y[n] = s + b[0];
}

// ---------------- launch ----------------
extern "C" void kernel_launch(void* const* d_in, const int* in_sizes, int n_in,
                              void* d_out, int out_size) {
    const int*       z      = (const int*)d_in[0];
    const float*     pos    = (const float*)d_in[1];
    const int*       ei     = (const int*)d_in[3];   // int32 (JAX x64 off)
    const float*     emb_w  = (const float*)d_in[4];
    const float*     emb2_w = (const float*)d_in[5];
    const float*     emb2_b = (const float*)d_in[6];
    const float*     dp1w   = (const float*)d_in[7];
    const float*     dp1b   = (const float*)d_in[8];
    const float*     dp2w   = (const float*)d_in[9];
    const float*     dp2b   = (const float*)d_in[10];
    const float*     dp3w   = (const float*)d_in[11];
    const float*     dp3b   = (const float*)d_in[12];
    const float*     lt0w   = (const float*)d_in[13];
    const float*     lt1w   = (const float*)d_in[14];
    const float*     lt2w   = (const float*)d_in[15];
    const float*     ls0w   = (const float*)d_in[16];
    const float*     ls0b   = (const float*)d_in[17];
    const float*     ls1w   = (const float*)d_in[18];
    const float*     ls1b   = (const float*)d_in[19];
    const float*     ing    = (const float*)d_in[20];
    const float*     inb    = (const float*)d_in[21];
    const float*     linw   = (const float*)d_in[22];
    const float*     linb   = (const float*)d_in[23];
    const float*     ong    = (const float*)d_in[24];
    const float*     onb    = (const float*)d_in[25];
    const float*     ol1w   = (const float*)d_in[26];
    const float*     ol1b   = (const float*)d_in[27];
    const float*     ol2w   = (const float*)d_in[28];
    const float*     ol2b   = (const float*)d_in[29];
    float* y = (float*)d_out;

    k_zero<<<20480, 256>>>();
    k_prep<<<128, 128>>>(emb_w, emb2_w, emb2_b);
    k_edge<<<NE, 128>>>(ei, pos, z, dp1w, dp1b, dp2w, dp2b, dp3w, dp3b);
    k_tnorm<<<NN, 128>>>(ing, inb);
    gemm_ls0<<<dim3(NN / 128, 4), 256>>>(ls0w, ls0b);
    gemm_ls1<<<dim3(NN / 128, 6), 256>>>(ls1w, ls1b);
    gemm_mixI<<<dim3(NN / 128, 2), 256>>>(lt0w);
    gemm_mixB<<<dim3(3 * NN / 128, 2), 256>>>(lt1w);
    gemm_mixS<<<dim3(6 * NN / 128, 2), 256>>>(lt2w);
    k_combine<<<(NN * 128) / 256, 256>>>();
    k_ln384<<<NN, 384>>>(ong, onb);
    gemm_lin<<<dim3(NN / 128, 2), 256>>>(linw, linb);
    gemm_ol1<<<dim3(NN / 128, 1), 256>>>(ol1w, ol1b);
    k_final<<<NN * 32 / 256, 256>>>(ol2w, ol2b, y);
}

// round 5
// speedup vs baseline: 1.2822x; 1.2822x over previous
#include <cuda_runtime.h>
#include <cuda_bf16.h>
#include <math.h>
#include <stdint.h>

#define NN 16384
#define NE 65536

// ---------------- scratch (static __device__, aligned) ----------------
static __device__ __align__(256) float g_U[128 * 128];
static __device__ __align__(256) float g_V[128 * 128];
static __device__ __align__(256) float g_acc[10][NN * 128];   // 0:a 1..3:b 4..9: m(xx,yy,zz,xy,xz,yz)
static __device__ __align__(256) float g_T[NN * 128];
static __device__ __align__(256) float g_H1[NN * 256];
static __device__ __align__(256) float g_NR[NN * 384];
static __device__ __align__(256) float g_mix[10][NN * 128];
static __device__ __align__(256) float g_X[NN * 384];
static __device__ __align__(256) float g_XN[NN * 384];
static __device__ __align__(256) float g_G1[NN * 128];
static __device__ __align__(256) float g_G2[NN * 64];

__device__ __forceinline__ float silu(float x) { return x / (1.f + expf(-x)); }

#define RBF_START 0.011108996538242306
#define RBF_BETA  (1.0 / ((0.0625 * (1.0 - RBF_START)) * (0.0625 * (1.0 - RBF_START))))
#define RBF_ALPHA (5.0 / 4.5)
#define PI_OVER_C 0.6981317007977318

// =================== warp-MMA (baseline PTX: ldmatrix + mma.sync bf16) ===================
__device__ __forceinline__ uint32_t smem_u32(const void* p) {
    uint32_t a;
    asm("{ .reg .u64 t; cvta.to.shared.u64 t, %1; cvt.u32.u64 %0, t; }" : "=r"(a) : "l"(p));
    return a;
}
__device__ __forceinline__ void ldm_x4(uint32_t addr, uint32_t* r) {
    asm volatile("ldmatrix.sync.aligned.m8n8.x4.shared.b16 {%0,%1,%2,%3}, [%4];"
                 : "=r"(r[0]), "=r"(r[1]), "=r"(r[2]), "=r"(r[3]) : "r"(addr));
}
__device__ __forceinline__ void ldm_x2(uint32_t addr, uint32_t* r) {
    asm volatile("ldmatrix.sync.aligned.m8n8.x2.shared.b16 {%0,%1}, [%2];"
                 : "=r"(r[0]), "=r"(r[1]) : "r"(addr));
}
__device__ __forceinline__ void mma16816(float* c, const uint32_t* a, const uint32_t* b) {
    asm volatile("mma.sync.aligned.m16n8k16.row.col.f32.bf16.bf16.f32 "
                 "{%0,%1,%2,%3}, {%4,%5,%6,%7}, {%8,%9}, {%0,%1,%2,%3};"
                 : "+f"(c[0]), "+f"(c[1]), "+f"(c[2]), "+f"(c[3])
                 : "r"(a[0]), "r"(a[1]), "r"(a[2]), "r"(a[3]), "r"(b[0]), "r"(b[1]));
}
// fp32 -> bf16 hi + bf16 lo (residual)
__device__ __forceinline__ void split4(float4 f, uint2& hv, uint2& lv) {
    __nv_bfloat162 h0 = __floats2bfloat162_rn(f.x, f.y);
    __nv_bfloat162 h1 = __floats2bfloat162_rn(f.z, f.w);
    __nv_bfloat162 l0 = __floats2bfloat162_rn(f.x - __bfloat162float(h0.x),
                                              f.y - __bfloat162float(h0.y));
    __nv_bfloat162 l1 = __floats2bfloat162_rn(f.z - __bfloat162float(h1.x),
                                              f.w - __bfloat162float(h1.y));
    hv = make_uint2(*(uint32_t*)&h0, *(uint32_t*)&h1);
    lv = make_uint2(*(uint32_t*)&l0, *(uint32_t*)&l1);
}

// SMEM: 4 tiles of 128 x 136 bf16 (row pad 8 -> 272B stride, 16B-aligned, ldmatrix conflict-free)
#define TPAD 136
#define TILE_B (128 * TPAD * 2)           // 34816
#define TG_SMEM (4 * TILE_B)              // 139264

// C[M,F] = A[M,K] @ W[F,K]^T (+bias)(+silu); hi/lo bf16 split, fp32 accum.
// blockIdx.x -> 128-row m tile, blockIdx.y -> 128-col f tile. 256 threads (8 warps: 4m x 2n).
__device__ __forceinline__ void mma_gemm_body(const float* __restrict__ A,
                                              const float* __restrict__ W,
                                              const float* __restrict__ bias,
                                              float* __restrict__ C,
                                              int K, int F, bool act) {
    extern __shared__ __align__(16) char smem[];
    __nv_bfloat16* aH = (__nv_bfloat16*)smem;
    __nv_bfloat16* aL = (__nv_bfloat16*)(smem + TILE_B);
    __nv_bfloat16* wH = (__nv_bfloat16*)(smem + 2 * TILE_B);
    __nv_bfloat16* wL = (__nv_bfloat16*)(smem + 3 * TILE_B);
    const uint32_t aH_u = smem_u32(aH), aL_u = smem_u32(aL);
    const uint32_t wH_u = smem_u32(wH), wL_u = smem_u32(wL);

    const int tid = threadIdx.x;
    const int lane = tid & 31, wid = tid >> 5;
    const int wm = wid & 3, wn = wid >> 2;
    const int m0 = blockIdx.x << 7;
    const int f0 = blockIdx.y << 7;

    float c[2][8][4];
    #pragma unroll
    for (int i = 0; i < 2; i++)
        #pragma unroll
        for (int j = 0; j < 8; j++)
            #pragma unroll
            for (int q = 0; q < 4; q++) c[i][j][q] = 0.f;

    // ldmatrix address components (within-tile)
    const int a_row = wm * 32 + (lane & 15);          // + mf*16
    const int a_col = (lane >> 4) << 3;               // + ks*16
    const int b_row = wn * 64 + (lane & 7);           // + nf*8
    const int b_col = ((lane >> 3) & 1) << 3;         // + ks*16

    for (int kc = 0; kc < K; kc += 128) {
        __syncthreads();
        // fill A/W hi+lo tiles: 128 rows x 32 float4
        const float* Ag = A + (size_t)m0 * K + kc;
        const float* Wg = W + (size_t)f0 * K + kc;
        #pragma unroll 4
        for (int i = tid; i < 128 * 32; i += 256) {
            int r = i >> 5, c4 = (i & 31) << 2;
            uint2 hv, lv;
            split4(*(const float4*)(Ag + (size_t)r * K + c4), hv, lv);
            *(uint2*)(aH + r * TPAD + c4) = hv;
            *(uint2*)(aL + r * TPAD + c4) = lv;
            split4(*(const float4*)(Wg + (size_t)r * K + c4), hv, lv);
            *(uint2*)(wH + r * TPAD + c4) = hv;
            *(uint2*)(wL + r * TPAD + c4) = lv;
        }
        __syncthreads();

        #pragma unroll
        for (int ks = 0; ks < 8; ks++) {
            uint32_t ah[2][4], al[2][4];
            #pragma unroll
            for (int mf = 0; mf < 2; mf++) {
                uint32_t off = ((a_row + mf * 16) * TPAD + a_col + ks * 16) * 2;
                ldm_x4(aH_u + off, ah[mf]);
                ldm_x4(aL_u + off, al[mf]);
            }
            #pragma unroll
            for (int nf = 0; nf < 8; nf++) {
                uint32_t boff = ((b_row + nf * 8) * TPAD + b_col + ks * 16) * 2;
                uint32_t bh[2], bl[2];
                ldm_x2(wH_u + boff, bh);
                ldm_x2(wL_u + boff, bl);
                #pragma unroll
                for (int mf = 0; mf < 2; mf++) {
                    mma16816(c[mf][nf], ah[mf], bh);   // aH*wH
                    mma16816(c[mf][nf], ah[mf], bl);   // aH*wL
                    mma16816(c[mf][nf], al[mf], bh);   // aL*wH
                }
            }
        }
    }

    // epilogue
    #pragma unroll
    for (int mf = 0; mf < 2; mf++) {
        #pragma unroll
        for (int nf = 0; nf < 8; nf++) {
            int grow = m0 + wm * 32 + mf * 16 + (lane >> 2);
            int gcol = f0 + wn * 64 + nf * 8 + ((lane & 3) << 1);
            float b0 = bias ? bias[gcol] : 0.f;
            float b1 = bias ? bias[gcol + 1] : 0.f;
            float v0 = c[mf][nf][0] + b0, v1 = c[mf][nf][1] + b1;
            float v2 = c[mf][nf][2] + b0, v3 = c[mf][nf][3] + b1;
            if (act) { v0 = silu(v0); v1 = silu(v1); v2 = silu(v2); v3 = silu(v3); }
            *(float2*)&C[(size_t)grow * F + gcol] = make_float2(v0, v1);
            *(float2*)&C[(size_t)(grow + 8) * F + gcol] = make_float2(v2, v3);
        }
    }
}

// mix: 10 planes of [NN,128]@[128,128]^T; W selected per 128-block plane group
__global__ __launch_bounds__(256, 1)
void tc_mix(const float* __restrict__ lt0w, const float* __restrict__ lt1w,
            const float* __restrict__ lt2w) {
    int plane = blockIdx.x >> 7;
    const float* W = (plane == 0) ? lt0w : (plane < 4 ? lt1w : lt2w);
    mma_gemm_body(&g_acc[0][0], W, nullptr, &g_mix[0][0], 128, 128, false);
}
__global__ __launch_bounds__(256, 1)
void tg_ls0(const float* __restrict__ W, const float* __restrict__ b) {
    mma_gemm_body(g_T, W, b, g_H1, 128, 256, true);
}
__global__ __launch_bounds__(256, 1)
void tg_ls1(const float* __restrict__ W, const float* __restrict__ b) {
    mma_gemm_body(g_H1, W, b, g_NR, 256, 384, true);
}
__global__ __launch_bounds__(256, 1)
void tg_lin(const float* __restrict__ W, const float* __restrict__ b) {
    mma_gemm_body(g_XN, W, b, g_G1, 384, 128, true);
}

// ---------------- zero accumulators ----------------
__global__ void k_zero() {
    size_t i = (size_t)blockIdx.x * blockDim.x + threadIdx.x;
    float4* p = (float4*)&g_acc[0][0];
    size_t n4 = (size_t)10 * NN * 128 / 4;
    if (i < n4) p[i] = make_float4(0.f, 0.f, 0.f, 0.f);
}

// ---------------- U/V lookup tables ----------------
__global__ void k_prep(const float* __restrict__ emb_w,
                       const float* __restrict__ emb2_w,
                       const float* __restrict__ emb2_b) {
    int zt = blockIdx.x;
    int h  = threadIdx.x;
    float u = emb2_b[h];
    float v = 0.f;
    #pragma unroll 4
    for (int k = 0; k < 128; k++) {
        float e = emb_w[zt * 128 + k];
        u = fmaf(e, emb2_w[h * 256 + k], u);
        v = fmaf(e, emb2_w[h * 256 + 128 + k], v);
    }
    g_U[zt * 128 + h] = u;
    g_V[zt * 128 + h] = v;
}

// ---------------- edge scatter ----------------
__global__ void k_edge(const int* __restrict__ ei,
                       const float* __restrict__ pos,
                       const int* __restrict__ z,
                       const float* __restrict__ dp1w, const float* __restrict__ dp1b,
                       const float* __restrict__ dp2w, const float* __restrict__ dp2b,
                       const float* __restrict__ dp3w, const float* __restrict__ dp3b) {
    int e = blockIdx.x;
    int h = threadIdx.x;
    int src = ei[e];
    int dst = ei[NE + e];
    float vx = pos[src * 3 + 0] - pos[dst * 3 + 0];
    float vy = pos[src * 3 + 1] - pos[dst * 3 + 1];
    float vz = pos[src * 3 + 2] - pos[dst * 3 + 2];
    float d = sqrtf(vx * vx + vy * vy + vz * vz);
    bool selfe = (src == dst);
    if (!selfe && !(d < 4.5f)) return;

    float cut = 0.5f * (cosf(d * (float)PI_OVER_C) + 1.0f);
    float inv = selfe ? 1.0f : (1.0f / d);
    vx *= inv; vy *= inv; vz *= inv;

    __shared__ __align__(16) float s_attr[32];
    if (h < 32) {
        float mean = (float)RBF_START + (float)h * (float)((1.0 - RBF_START) / 31.0);
        float g = expf(-(float)RBF_ALPHA * d);
        float diff = g - mean;
        s_attr[h] = cut * expf(-(float)RBF_BETA * diff * diff);
    }
    __syncthreads();

    float Z = g_U[(z[src] << 7) + h] + g_V[(z[dst] << 7) + h];
    float C = cut * Z;

    float d1 = dp1b[h], d2 = dp2b[h], d3 = dp3b[h];
    #pragma unroll
    for (int r = 0; r < 32; r += 4) {
        float4 a4 = *(const float4*)&s_attr[r];
        float4 w1 = *(const float4*)&dp1w[h * 32 + r];
        float4 w2 = *(const float4*)&dp2w[h * 32 + r];
        float4 w3 = *(const float4*)&dp3w[h * 32 + r];
        d1 += a4.x * w1.x + a4.y * w1.y + a4.z * w1.z + a4.w * w1.w;
        d2 += a4.x * w2.x + a4.y * w2.y + a4.z * w2.z + a4.w * w2.w;
        d3 += a4.x * w3.x + a4.y * w3.y + a4.z * w3.z + a4.w * w3.w;
    }
    float a  = d1 * C;
    float cb = d2 * C;
    float cs = d3 * C;
    int i = (src << 7) + h;
    atomicAdd(&g_acc[0][i], a);
    atomicAdd(&g_acc[1][i], cb * vx);
    atomicAdd(&g_acc[2][i], cb * vy);
    atomicAdd(&g_acc[3][i], cb * vz);
    atomicAdd(&g_acc[4][i], cs * vx * vx);
    atomicAdd(&g_acc[5][i], cs * vy * vy);
    atomicAdd(&g_acc[6][i], cs * vz * vz);
    atomicAdd(&g_acc[7][i], cs * vx * vy);
    atomicAdd(&g_acc[8][i], cs * vx * vz);
    atomicAdd(&g_acc[9][i], cs * vy * vz);
}

// ---------------- tensor norm + layernorm(128) ----------------
__global__ void k_tnorm(const float* __restrict__ gam, const float* __restrict__ bet) {
    int n = blockIdx.x, h = threadIdx.x;
    int i = (n << 7) + h;
    float a  = g_acc[0][i];
    float bx = g_acc[1][i], by = g_acc[2][i], bz = g_acc[3][i];
    float xx = g_acc[4][i], yy = g_acc[5][i], zz = g_acc[6][i];
    float xy = g_acc[7][i], xz = g_acc[8][i], yz = g_acc[9][i];
    float tr = xx + yy + zz;
    float ms = xx * xx + yy * yy + zz * zz + 2.f * (xy * xy + xz * xz + yz * yz);
    float tn = 3.f * a * a + 2.f * (bx * bx + by * by + bz * bz) + ms - tr * tr * (1.f / 3.f);

    __shared__ float red[4];
    float v = tn;
    #pragma unroll
    for (int o = 16; o; o >>= 1) v += __shfl_xor_sync(0xffffffffu, v, o);
    if ((h & 31) == 0) red[h >> 5] = v;
    __syncthreads();
    float mean = (red[0] + red[1] + red[2] + red[3]) * (1.f / 128.f);
    __syncthreads();
    float dev = tn - mean;
    v = dev * dev;
    #pragma unroll
    for (int o = 16; o; o >>= 1) v += __shfl_xor_sync(0xffffffffu, v, o);
    if ((h & 31) == 0) red[h >> 5] = v;
    __syncthreads();
    float var = (red[0] + red[1] + red[2] + red[3]) * (1.f / 128.f);
    g_T[i] = dev * rsqrtf(var + 1e-5f) * gam[h] + bet[h];
}

// ---------------- SIMT SGEMM (ol1 only: F=64) ----------------
__device__ __forceinline__ void sgemm_body(const float* __restrict__ A,
                                           const float* __restrict__ W,
                                           const float* __restrict__ bias,
                                           float* __restrict__ C,
                                           int K, int F, bool act) {
    __shared__ __align__(16) float As[8][128];
    __shared__ __align__(16) float Ws[8][64];
    const int tid = threadIdx.x;
    const int tx = tid & 15, ty = tid >> 4;
    const int m0 = blockIdx.x << 7;
    const int f0 = blockIdx.y << 6;
    float acc[8][4];
    #pragma unroll
    for (int i = 0; i < 8; i++)
        #pragma unroll
        for (int j = 0; j < 4; j++) acc[i][j] = 0.f;

    const int arow = tid >> 1, acol = (tid & 1) << 2;
    const int wrow = (tid & 127) >> 1, wcol = acol;
    const float* Ag = A + (size_t)(m0 + arow) * K + acol;
    const float* Wg = W + (size_t)(f0 + wrow) * K + wcol;

    for (int k0 = 0; k0 < K; k0 += 8) {
        float4 av = *(const float4*)(Ag + k0);
        As[acol + 0][arow] = av.x; As[acol + 1][arow] = av.y;
        As[acol + 2][arow] = av.z; As[acol + 3][arow] = av.w;
        if (tid < 128) {
            float4 wv = *(const float4*)(Wg + k0);
            Ws[wcol + 0][wrow] = wv.x; Ws[wcol + 1][wrow] = wv.y;
            Ws[wcol + 2][wrow] = wv.z; Ws[wcol + 3][wrow] = wv.w;
        }
        __syncthreads();
        #pragma unroll
        for (int k = 0; k < 8; k++) {
            float4 a0 = *(const float4*)&As[k][ty << 3];
            float4 a1 = *(const float4*)&As[k][(ty << 3) + 4];
            float4 wv = *(const float4*)&Ws[k][tx << 2];
            float am[8] = {a0.x, a0.y, a0.z, a0.w, a1.x, a1.y, a1.z, a1.w};
            float wn[4] = {wv.x, wv.y, wv.z, wv.w};
            #pragma unroll
            for (int i = 0; i < 8; i++)
                #pragma unroll
                for (int j = 0; j < 4; j++)
                    acc[i][j] = fmaf(am[i], wn[j], acc[i][j]);
        }
        __syncthreads();
    }

    float bj[4];
    #pragma unroll
    for (int j = 0; j < 4; j++) bj[j] = bias ? bias[f0 + (tx << 2) + j] : 0.f;
    #pragma unroll
    for (int i = 0; i < 8; i++) {
        float v0 = acc[i][0] + bj[0];
        float v1 = acc[i][1] + bj[1];
        float v2 = acc[i][2] + bj[2];
        float v3 = acc[i][3] + bj[3];
        if (act) { v0 = silu(v0); v1 = silu(v1); v2 = silu(v2); v3 = silu(v3); }
        *(float4*)&C[(size_t)(m0 + (ty << 3) + i) * F + f0 + (tx << 2)] =
            make_float4(v0, v1, v2, v3);
    }
}

__global__ void gemm_ol1(const float* W, const float* b) { sgemm_body(g_G1, W, b, g_G2, 128, 64, true); }

// ---------------- combine mixed comps into x[N,384] ----------------
__global__ void k_combine() {
    int idx = blockIdx.x * 256 + threadIdx.x;
    if (idx >= NN * 128) return;
    int n = idx >> 7, k = idx & 127;
    float Ip = g_mix[0][idx];
    float B0 = g_mix[1][idx], B1 = g_mix[2][idx], B2 = g_mix[3][idx];
    float xx = g_mix[4][idx], yy = g_mix[5][idx], zz = g_mix[6][idx];
    float xy = g_mix[7][idx], xz = g_mix[8][idx], yz = g_mix[9][idx];
    const float* nr = &g_NR[n * 384 + 3 * k];
    float n0 = nr[0], n1 = nr[1], n2 = nr[2];
    float t  = Ip * n0;
    float x0 = 3.f * t * t;
    float bb = B0 * B0 + B1 * B1 + B2 * B2;
    float x1 = 2.f * bb * n1 * n1;
    float tr = xx + yy + zz;
    float ms = xx * xx + yy * yy + zz * zz + 2.f * (xy * xy + xz * xz + yz * yz);
    float x2 = (ms - tr * tr * (1.f / 3.f)) * n2 * n2;
    g_X[n * 384 + k]       = x0;
    g_X[n * 384 + 128 + k] = x1;
    g_X[n * 384 + 256 + k] = x2;
}

// ---------------- layernorm over 384 ----------------
__global__ void k_ln384(const float* __restrict__ gam, const float* __restrict__ bet) {
    int n = blockIdx.x, j = threadIdx.x;
    float x = g_X[n * 384 + j];
    __shared__ float red[12];
    float v = x;
    #pragma unroll
    for (int o = 16; o; o >>= 1) v += __shfl_xor_sync(0xffffffffu, v, o);
    if ((j & 31) == 0) red[j >> 5] = v;
    __syncthreads();
    float s = 0.f;
    #pragma unroll
    for (int w = 0; w < 12; w++) s += red[w];
    float mean = s * (1.f / 384.f);
    __syncthreads();
    float dev = x - mean;
    v = dev * dev;
    #pragma unroll
    for (int o = 16; o; o >>= 1) v += __shfl_xor_sync(0xffffffffu, v, o);
    if ((j & 31) == 0) red[j >> 5] = v;
    __syncthreads();
    s = 0.f;
    #pragma unroll
    for (int w = 0; w < 12; w++) s += red[w];
    float var = s * (1.f / 384.f);
    g_XN[n * 384 + j] = dev * rsqrtf(var + 1e-5f) * gam[j] + bet[j];
}

// ---------------- final ----------------
__global__ void k_final(const float* __restrict__ w, const float* __restrict__ b,
                        float* __restrict__ y) {
    int gi = blockIdx.x * 256 + threadIdx.x;
    int n = gi >> 5, lane = gi & 31;
    if (n >= NN) return;
    float s = g_G2[n * 64 + lane] * w[lane] + g_G2[n * 64 + 32 + lane] * w[32 + lane];
    #pragma unroll
    for (int o = 16; o; o >>= 1) s += __shfl_xor_sync(0xffffffffu, s, o);
    if (lane == 0) y[n] = s + b[0];
}

// ---------------- launch ----------------
extern "C" void kernel_launch(void* const* d_in, const int* in_sizes, int n_in,
                              void* d_out, int out_size) {
    const int*   z      = (const int*)d_in[0];
    const float* pos    = (const float*)d_in[1];
    const int*   ei     = (const int*)d_in[3];
    const float* emb_w  = (const float*)d_in[4];
    const float* emb2_w = (const float*)d_in[5];
    const float* emb2_b = (const float*)d_in[6];
    const float* dp1w   = (const float*)d_in[7];
    const float* dp1b   = (const float*)d_in[8];
    const float* dp2w   = (const float*)d_in[9];
    const float* dp2b   = (const float*)d_in[10];
    const float* dp3w   = (const float*)d_in[11];
    const float* dp3b   = (const float*)d_in[12];
    const float* lt0w   = (const float*)d_in[13];
    const float* lt1w   = (const float*)d_in[14];
    const float* lt2w   = (const float*)d_in[15];
    const float* ls0w   = (const float*)d_in[16];
    const float* ls0b   = (const float*)d_in[17];
    const float* ls1w   = (const float*)d_in[18];
    const float* ls1b   = (const float*)d_in[19];
    const float* ing    = (const float*)d_in[20];
    const float* inb    = (const float*)d_in[21];
    const float* linw   = (const float*)d_in[22];
    const float* linb   = (const float*)d_in[23];
    const float* ong    = (const float*)d_in[24];
    const float* onb    = (const float*)d_in[25];
    const float* ol1w   = (const float*)d_in[26];
    const float* ol1b   = (const float*)d_in[27];
    const float* ol2w   = (const float*)d_in[28];
    const float* ol2b   = (const float*)d_in[29];
    float* y = (float*)d_out;

    cudaFuncSetAttribute(tc_mix, cudaFuncAttributeMaxDynamicSharedMemorySize, TG_SMEM);
    cudaFuncSetAttribute(tg_ls0, cudaFuncAttributeMaxDynamicSharedMemorySize, TG_SMEM);
    cudaFuncSetAttribute(tg_ls1, cudaFuncAttributeMaxDynamicSharedMemorySize, TG_SMEM);
    cudaFuncSetAttribute(tg_lin, cudaFuncAttributeMaxDynamicSharedMemorySize, TG_SMEM);

    k_zero<<<20480, 256>>>();
    k_prep<<<128, 128>>>(emb_w, emb2_w, emb2_b);
    k_edge<<<NE, 128>>>(ei, pos, z, dp1w, dp1b, dp2w, dp2b, dp3w, dp3b);
    k_tnorm<<<NN, 128>>>(ing, inb);
    tg_ls0<<<dim3(NN / 128, 2), 256, TG_SMEM>>>(ls0w, ls0b);
    tg_ls1<<<dim3(NN / 128, 3), 256, TG_SMEM>>>(ls1w, ls1b);
    tc_mix<<<dim3(10 * NN / 128, 1), 256, TG_SMEM>>>(lt0w, lt1w, lt2w);
    k_combine<<<(NN * 128) / 256, 256>>>();
    k_ln384<<<NN, 384>>>(ong, onb);
    tg_lin<<<dim3(NN / 128, 1), 256, TG_SMEM>>>(linw, linb);
    gemm_ol1<<<dim3(NN / 128, 1), 256>>>(ol1w, ol1b);
    k_final<<<NN * 32 / 256, 256>>>(ol2w, ol2b, y);
}

// round 6
// speedup vs baseline: 1.3633x; 1.0633x over previous
#include <cuda_runtime.h>
#include <cuda_bf16.h>
#include <math.h>
#include <stdint.h>

#define NN 16384
#define NE 65536

// ---------------- scratch (static __device__, aligned) ----------------
static __device__ __align__(256) float g_U[128 * 128];
static __device__ __align__(256) float g_V[128 * 128];
static __device__ __align__(256) float g_acc[10][NN * 128];   // 0:a 1..3:b 4..9: m(xx,yy,zz,xy,xz,yz)
static __device__ __align__(256) float g_T[NN * 128];
static __device__ __align__(256) float g_H1[NN * 256];
static __device__ __align__(256) float g_NR[NN * 384];
static __device__ __align__(256) float g_mix[10][NN * 128];
static __device__ __align__(256) float g_XN[NN * 384];
static __device__ __align__(256) float g_G1[NN * 128];
static __device__ __align__(256) float g_G2[NN * 64];

// CSR edge compaction
static __device__ __align__(256) int    g_cnt[NN];
static __device__ __align__(256) int    g_off[NN];
static __device__ __align__(256) int    g_fill[NN];
static __device__ __align__(256) float4 g_erec[NE];   // vx,vy,vz,d (unnormalized)
static __device__ __align__(256) int    g_ez[NE];     // z[dst] | (selfe<<31)

__device__ __forceinline__ float silu(float x) { return x / (1.f + expf(-x)); }

#define RBF_START 0.011108996538242306
#define RBF_BETA  (1.0 / ((0.0625 * (1.0 - RBF_START)) * (0.0625 * (1.0 - RBF_START))))
#define RBF_ALPHA (5.0 / 4.5)
#define PI_OVER_C 0.6981317007977318

// =================== warp-MMA (baseline PTX: ldmatrix + mma.sync bf16) ===================
__device__ __forceinline__ uint32_t smem_u32(const void* p) {
    uint32_t a;
    asm("{ .reg .u64 t; cvta.to.shared.u64 t, %1; cvt.u32.u64 %0, t; }" : "=r"(a) : "l"(p));
    return a;
}
__device__ __forceinline__ void ldm_x4(uint32_t addr, uint32_t* r) {
    asm volatile("ldmatrix.sync.aligned.m8n8.x4.shared.b16 {%0,%1,%2,%3}, [%4];"
                 : "=r"(r[0]), "=r"(r[1]), "=r"(r[2]), "=r"(r[3]) : "r"(addr));
}
__device__ __forceinline__ void ldm_x2(uint32_t addr, uint32_t* r) {
    asm volatile("ldmatrix.sync.aligned.m8n8.x2.shared.b16 {%0,%1}, [%2];"
                 : "=r"(r[0]), "=r"(r[1]) : "r"(addr));
}
__device__ __forceinline__ void mma16816(float* c, const uint32_t* a, const uint32_t* b) {
    asm volatile("mma.sync.aligned.m16n8k16.row.col.f32.bf16.bf16.f32 "
                 "{%0,%1,%2,%3}, {%4,%5,%6,%7}, {%8,%9}, {%0,%1,%2,%3};"
                 : "+f"(c[0]), "+f"(c[1]), "+f"(c[2]), "+f"(c[3])
                 : "r"(a[0]), "r"(a[1]), "r"(a[2]), "r"(a[3]), "r"(b[0]), "r"(b[1]));
}
__device__ __forceinline__ void split4(float4 f, uint2& hv, uint2& lv) {
    __nv_bfloat162 h0 = __floats2bfloat162_rn(f.x, f.y);
    __nv_bfloat162 h1 = __floats2bfloat162_rn(f.z, f.w);
    __nv_bfloat162 l0 = __floats2bfloat162_rn(f.x - __bfloat162float(h0.x),
                                              f.y - __bfloat162float(h0.y));
    __nv_bfloat162 l1 = __floats2bfloat162_rn(f.z - __bfloat162float(h1.x),
                                              f.w - __bfloat162float(h1.y));
    hv = make_uint2(*(uint32_t*)&h0, *(uint32_t*)&h1);
    lv = make_uint2(*(uint32_t*)&l0, *(uint32_t*)&l1);
}

#define TPAD 136
#define TILE_B (128 * TPAD * 2)
#define TG_SMEM (4 * TILE_B)

__device__ __forceinline__ void mma_gemm_body(const float* __restrict__ A,
                                              const float* __restrict__ W,
                                              const float* __restrict__ bias,
                                              float* __restrict__ C,
                                              int K, int F, bool act) {
    extern __shared__ __align__(16) char smem[];
    __nv_bfloat16* aH = (__nv_bfloat16*)smem;
    __nv_bfloat16* aL = (__nv_bfloat16*)(smem + TILE_B);
    __nv_bfloat16* wH = (__nv_bfloat16*)(smem + 2 * TILE_B);
    __nv_bfloat16* wL = (__nv_bfloat16*)(smem + 3 * TILE_B);
    const uint32_t aH_u = smem_u32(aH), aL_u = smem_u32(aL);
    const uint32_t wH_u = smem_u32(wH), wL_u = smem_u32(wL);

    const int tid = threadIdx.x;
    const int lane = tid & 31, wid = tid >> 5;
    const int wm = wid & 3, wn = wid >> 2;
    const int m0 = blockIdx.x << 7;
    const int f0 = blockIdx.y << 7;

    float c[2][8][4];
    #pragma unroll
    for (int i = 0; i < 2; i++)
        #pragma unroll
        for (int j = 0; j < 8; j++)
            #pragma unroll
            for (int q = 0; q < 4; q++) c[i][j][q] = 0.f;

    const int a_row = wm * 32 + (lane & 15);
    const int a_col = (lane >> 4) << 3;
    const int b_row = wn * 64 + (lane & 7);
    const int b_col = ((lane >> 3) & 1) << 3;

    for (int kc = 0; kc < K; kc += 128) {
        __syncthreads();
        const float* Ag = A + (size_t)m0 * K + kc;
        const float* Wg = W + (size_t)f0 * K + kc;
        #pragma unroll 4
        for (int i = tid; i < 128 * 32; i += 256) {
            int r = i >> 5, c4 = (i & 31) << 2;
            uint2 hv, lv;
            split4(*(const float4*)(Ag + (size_t)r * K + c4), hv, lv);
            *(uint2*)(aH + r * TPAD + c4) = hv;
            *(uint2*)(aL + r * TPAD + c4) = lv;
            split4(*(const float4*)(Wg + (size_t)r * K + c4), hv, lv);
            *(uint2*)(wH + r * TPAD + c4) = hv;
            *(uint2*)(wL + r * TPAD + c4) = lv;
        }
        __syncthreads();

        #pragma unroll
        for (int ks = 0; ks < 8; ks++) {
            uint32_t ah[2][4], al[2][4];
            #pragma unroll
            for (int mf = 0; mf < 2; mf++) {
                uint32_t off = ((a_row + mf * 16) * TPAD + a_col + ks * 16) * 2;
                ldm_x4(aH_u + off, ah[mf]);
                ldm_x4(aL_u + off, al[mf]);
            }
            #pragma unroll
            for (int nf = 0; nf < 8; nf++) {
                uint32_t boff = ((b_row + nf * 8) * TPAD + b_col + ks * 16) * 2;
                uint32_t bh[2], bl[2];
                ldm_x2(wH_u + boff, bh);
                ldm_x2(wL_u + boff, bl);
                #pragma unroll
                for (int mf = 0; mf < 2; mf++) {
                    mma16816(c[mf][nf], ah[mf], bh);
                    mma16816(c[mf][nf], ah[mf], bl);
                    mma16816(c[mf][nf], al[mf], bh);
                }
            }
        }
    }

    #pragma unroll
    for (int mf = 0; mf < 2; mf++) {
        #pragma unroll
        for (int nf = 0; nf < 8; nf++) {
            int grow = m0 + wm * 32 + mf * 16 + (lane >> 2);
            int gcol = f0 + wn * 64 + nf * 8 + ((lane & 3) << 1);
            float b0 = bias ? bias[gcol] : 0.f;
            float b1 = bias ? bias[gcol + 1] : 0.f;
            float v0 = c[mf][nf][0] + b0, v1 = c[mf][nf][1] + b1;
            float v2 = c[mf][nf][2] + b0, v3 = c[mf][nf][3] + b1;
            if (act) { v0 = silu(v0); v1 = silu(v1); v2 = silu(v2); v3 = silu(v3); }
            *(float2*)&C[(size_t)grow * F + gcol] = make_float2(v0, v1);
            *(float2*)&C[(size_t)(grow + 8) * F + gcol] = make_float2(v2, v3);
        }
    }
}

__global__ __launch_bounds__(256, 1)
void tc_mix(const float* __restrict__ lt0w, const float* __restrict__ lt1w,
            const float* __restrict__ lt2w) {
    int plane = blockIdx.x >> 7;
    const float* W = (plane == 0) ? lt0w : (plane < 4 ? lt1w : lt2w);
    mma_gemm_body(&g_acc[0][0], W, nullptr, &g_mix[0][0], 128, 128, false);
}
__global__ __launch_bounds__(256, 1)
void tg_ls0(const float* __restrict__ W, const float* __restrict__ b) {
    mma_gemm_body(g_T, W, b, g_H1, 128, 256, true);
}
__global__ __launch_bounds__(256, 1)
void tg_ls1(const float* __restrict__ W, const float* __restrict__ b) {
    mma_gemm_body(g_H1, W, b, g_NR, 256, 384, true);
}
__global__ __launch_bounds__(256, 1)
void tg_lin(const float* __restrict__ W, const float* __restrict__ b) {
    mma_gemm_body(g_XN, W, b, g_G1, 384, 128, true);
}

// ---------------- U/V lookup tables ----------------
__global__ void k_prep(const float* __restrict__ emb_w,
                       const float* __restrict__ emb2_w,
                       const float* __restrict__ emb2_b) {
    int zt = blockIdx.x;
    int h  = threadIdx.x;
    float u = emb2_b[h];
    float v = 0.f;
    #pragma unroll 4
    for (int k = 0; k < 128; k++) {
        float e = emb_w[zt * 128 + k];
        u = fmaf(e, emb2_w[h * 256 + k], u);
        v = fmaf(e, emb2_w[h * 256 + 128 + k], v);
    }
    g_U[zt * 128 + h] = u;
    g_V[zt * 128 + h] = v;
}

// =================== CSR edge compaction ===================
__global__ void k_zero_cnt() {
    int i = blockIdx.x * 256 + threadIdx.x;
    if (i < NN) { g_cnt[i] = 0; g_fill[i] = 0; }
}

__global__ void k_count(const int* __restrict__ ei, const float* __restrict__ pos) {
    int e = blockIdx.x * 256 + threadIdx.x;
    if (e >= NE) return;
    int src = ei[e], dst = ei[NE + e];
    float vx = pos[src * 3 + 0] - pos[dst * 3 + 0];
    float vy = pos[src * 3 + 1] - pos[dst * 3 + 1];
    float vz = pos[src * 3 + 2] - pos[dst * 3 + 2];
    float d = sqrtf(vx * vx + vy * vy + vz * vz);
    if (src == dst || d < 4.5f) atomicAdd(&g_cnt[src], 1);
}

// exclusive scan over g_cnt -> g_off (one block, 1024 thr x 16)
__global__ void k_scan() {
    __shared__ int ps[1024];
    int t = threadIdx.x;
    int base = t * 16;
    int local[16];
    int s = 0;
    #pragma unroll
    for (int i = 0; i < 16; i++) { local[i] = s; s += g_cnt[base + i]; }
    ps[t] = s;
    __syncthreads();
    #pragma unroll
    for (int off = 1; off < 1024; off <<= 1) {
        int v = (t >= off) ? ps[t - off] : 0;
        __syncthreads();
        ps[t] += v;
        __syncthreads();
    }
    int pre = (t == 0) ? 0 : ps[t - 1];
    #pragma unroll
    for (int i = 0; i < 16; i++) g_off[base + i] = pre + local[i];
}

__global__ void k_scatter(const int* __restrict__ ei, const float* __restrict__ pos,
                          const int* __restrict__ z) {
    int e = blockIdx.x * 256 + threadIdx.x;
    if (e >= NE) return;
    int src = ei[e], dst = ei[NE + e];
    float vx = pos[src * 3 + 0] - pos[dst * 3 + 0];
    float vy = pos[src * 3 + 1] - pos[dst * 3 + 1];
    float vz = pos[src * 3 + 2] - pos[dst * 3 + 2];
    float d = sqrtf(vx * vx + vy * vy + vz * vz);
    bool selfe = (src == dst);
    if (!selfe && !(d < 4.5f)) return;
    int slot = g_off[src] + atomicAdd(&g_fill[src], 1);
    g_erec[slot] = make_float4(vx, vy, vz, d);
    g_ez[slot] = z[dst] | (selfe ? (int)0x80000000 : 0);
}

// =================== gather + tensor-norm + layernorm(128), fused ===================
__global__ void k_gather(const int* __restrict__ z,
                         const float* __restrict__ dp1w, const float* __restrict__ dp1b,
                         const float* __restrict__ dp2w, const float* __restrict__ dp2b,
                         const float* __restrict__ dp3w, const float* __restrict__ dp3b,
                         const float* __restrict__ gam, const float* __restrict__ bet) {
    int n = blockIdx.x, h = threadIdx.x;
    __shared__ __align__(16) float s_attr[32];
    __shared__ float red[4];

    int cnt = g_cnt[n];
    int off = g_off[n];
    int zn = z[n];
    float Un = g_U[(zn << 7) + h];
    float b1h = dp1b[h], b2h = dp2b[h], b3h = dp3b[h];

    float a = 0.f, bx = 0.f, by = 0.f, bz = 0.f;
    float xx = 0.f, yy = 0.f, zz = 0.f, xy = 0.f, xz = 0.f, yz = 0.f;

    for (int j = 0; j < cnt; j++) {
        float4 rec = g_erec[off + j];
        int ezd = g_ez[off + j];
        bool selfe = (ezd < 0);
        int zdst = ezd & 127;
        float d = rec.w;
        float cut = 0.5f * (cosf(d * (float)PI_OVER_C) + 1.0f);
        float inv = selfe ? 1.0f : (1.0f / d);
        float vx = rec.x * inv, vy = rec.y * inv, vz = rec.z * inv;

        __syncthreads();
        if (h < 32) {
            float mean = (float)RBF_START + (float)h * (float)((1.0 - RBF_START) / 31.0);
            float g = expf(-(float)RBF_ALPHA * d);
            float diff = g - mean;
            s_attr[h] = cut * expf(-(float)RBF_BETA * diff * diff);
        }
        __syncthreads();

        float C = cut * (Un + g_V[(zdst << 7) + h]);
        float d1 = b1h, d2 = b2h, d3 = b3h;
        #pragma unroll
        for (int r = 0; r < 32; r += 4) {
            float4 a4 = *(const float4*)&s_attr[r];
            float4 w1 = *(const float4*)&dp1w[h * 32 + r];
            float4 w2 = *(const float4*)&dp2w[h * 32 + r];
            float4 w3 = *(const float4*)&dp3w[h * 32 + r];
            d1 += a4.x * w1.x + a4.y * w1.y + a4.z * w1.z + a4.w * w1.w;
            d2 += a4.x * w2.x + a4.y * w2.y + a4.z * w2.z + a4.w * w2.w;
            d3 += a4.x * w3.x + a4.y * w3.y + a4.z * w3.z + a4.w * w3.w;
        }
        float ai = d1 * C, cb = d2 * C, cs = d3 * C;
        a  += ai;
        bx += cb * vx; by += cb * vy; bz += cb * vz;
        xx += cs * vx * vx; yy += cs * vy * vy; zz += cs * vz * vz;
        xy += cs * vx * vy; xz += cs * vx * vz; yz += cs * vy * vz;
    }

    int i = (n << 7) + h;
    g_acc[0][i] = a;
    g_acc[1][i] = bx; g_acc[2][i] = by; g_acc[3][i] = bz;
    g_acc[4][i] = xx; g_acc[5][i] = yy; g_acc[6][i] = zz;
    g_acc[7][i] = xy; g_acc[8][i] = xz; g_acc[9][i] = yz;

    // tensor norm + layernorm(128)
    float tr = xx + yy + zz;
    float ms = xx * xx + yy * yy + zz * zz + 2.f * (xy * xy + xz * xz + yz * yz);
    float tn = 3.f * a * a + 2.f * (bx * bx + by * by + bz * bz) + ms - tr * tr * (1.f / 3.f);

    float v = tn;
    #pragma unroll
    for (int o = 16; o; o >>= 1) v += __shfl_xor_sync(0xffffffffu, v, o);
    __syncthreads();
    if ((h & 31) == 0) red[h >> 5] = v;
    __syncthreads();
    float mean = (red[0] + red[1] + red[2] + red[3]) * (1.f / 128.f);
    float dev = tn - mean;
    v = dev * dev;
    #pragma unroll
    for (int o = 16; o; o >>= 1) v += __shfl_xor_sync(0xffffffffu, v, o);
    __syncthreads();
    if ((h & 31) == 0) red[h >> 5] = v;
    __syncthreads();
    float var = (red[0] + red[1] + red[2] + red[3]) * (1.f / 128.f);
    g_T[i] = dev * rsqrtf(var + 1e-5f) * gam[h] + bet[h];
}

// ---------------- SIMT SGEMM (ol1 only: F=64) ----------------
__device__ __forceinline__ void sgemm_body(const float* __restrict__ A,
                                           const float* __restrict__ W,
                                           const float* __restrict__ bias,
                                           float* __restrict__ C,
                                           int K, int F, bool act) {
    __shared__ __align__(16) float As[8][128];
    __shared__ __align__(16) float Ws[8][64];
    const int tid = threadIdx.x;
    const int tx = tid & 15, ty = tid >> 4;
    const int m0 = blockIdx.x << 7;
    const int f0 = blockIdx.y << 6;
    float acc[8][4];
    #pragma unroll
    for (int i = 0; i < 8; i++)
        #pragma unroll
        for (int j = 0; j < 4; j++) acc[i][j] = 0.f;

    const int arow = tid >> 1, acol = (tid & 1) << 2;
    const int wrow = (tid & 127) >> 1, wcol = acol;
    const float* Ag = A + (size_t)(m0 + arow) * K + acol;
    const float* Wg = W + (size_t)(f0 + wrow) * K + wcol;

    for (int k0 = 0; k0 < K; k0 += 8) {
        float4 av = *(const float4*)(Ag + k0);
        As[acol + 0][arow] = av.x; As[acol + 1][arow] = av.y;
        As[acol + 2][arow] = av.z; As[acol + 3][arow] = av.w;
        if (tid < 128) {
            float4 wv = *(const float4*)(Wg + k0);
            Ws[wcol + 0][wrow] = wv.x; Ws[wcol + 1][wrow] = wv.y;
            Ws[wcol + 2][wrow] = wv.z; Ws[wcol + 3][wrow] = wv.w;
        }
        __syncthreads();
        #pragma unroll
        for (int k = 0; k < 8; k++) {
            float4 a0 = *(const float4*)&As[k][ty << 3];
            float4 a1 = *(const float4*)&As[k][(ty << 3) + 4];
            float4 wv = *(const float4*)&Ws[k][tx << 2];
            float am[8] = {a0.x, a0.y, a0.z, a0.w, a1.x, a1.y, a1.z, a1.w};
            float wn[4] = {wv.x, wv.y, wv.z, wv.w};
            #pragma unroll
            for (int i = 0; i < 8; i++)
                #pragma unroll
                for (int j = 0; j < 4; j++)
                    acc[i][j] = fmaf(am[i], wn[j], acc[i][j]);
        }
        __syncthreads();
    }

    float bj[4];
    #pragma unroll
    for (int j = 0; j < 4; j++) bj[j] = bias ? bias[f0 + (tx << 2) + j] : 0.f;
    #pragma unroll
    for (int i = 0; i < 8; i++) {
        float v0 = acc[i][0] + bj[0];
        float v1 = acc[i][1] + bj[1];
        float v2 = acc[i][2] + bj[2];
        float v3 = acc[i][3] + bj[3];
        if (act) { v0 = silu(v0); v1 = silu(v1); v2 = silu(v2); v3 = silu(v3); }
        *(float4*)&C[(size_t)(m0 + (ty << 3) + i) * F + f0 + (tx << 2)] =
            make_float4(v0, v1, v2, v3);
    }
}

__global__ void gemm_ol1(const float* W, const float* b) { sgemm_body(g_G1, W, b, g_G2, 128, 64, true); }

// ---------------- combine + layernorm(384), fused (block = node, 128 thr) ----------------
__global__ void k_combine_ln(const float* __restrict__ gam, const float* __restrict__ bet) {
    int n = blockIdx.x, k = threadIdx.x;
    int idx = (n << 7) + k;
    float Ip = g_mix[0][idx];
    float B0 = g_mix[1][idx], B1 = g_mix[2][idx], B2 = g_mix[3][idx];
    float xx = g_mix[4][idx], yy = g_mix[5][idx], zz = g_mix[6][idx];
    float xy = g_mix[7][idx], xz = g_mix[8][idx], yz = g_mix[9][idx];
    const float* nr = &g_NR[n * 384 + 3 * k];
    float n0 = nr[0], n1 = nr[1], n2 = nr[2];
    float t  = Ip * n0;
    float x0 = 3.f * t * t;
    float bb = B0 * B0 + B1 * B1 + B2 * B2;
    float x1 = 2.f * bb * n1 * n1;
    float tr = xx + yy + zz;
    float ms = xx * xx + yy * yy + zz * zz + 2.f * (xy * xy + xz * xz + yz * yz);
    float x2 = (ms - tr * tr * (1.f / 3.f)) * n2 * n2;

    __shared__ float red[4];
    float v = x0 + x1 + x2;
    #pragma unroll
    for (int o = 16; o; o >>= 1) v += __shfl_xor_sync(0xffffffffu, v, o);
    if ((k & 31) == 0) red[k >> 5] = v;
    __syncthreads();
    float mean = (red[0] + red[1] + red[2] + red[3]) * (1.f / 384.f);
    __syncthreads();
    float d0 = x0 - mean, d1 = x1 - mean, d2 = x2 - mean;
    v = d0 * d0 + d1 * d1 + d2 * d2;
    #pragma unroll
    for (int o = 16; o; o >>= 1) v += __shfl_xor_sync(0xffffffffu, v, o);
    if ((k & 31) == 0) red[k >> 5] = v;
    __syncthreads();
    float var = (red[0] + red[1] + red[2] + red[3]) * (1.f / 384.f);
    float rs = rsqrtf(var + 1e-5f);
    g_XN[n * 384 + k]       = d0 * rs * gam[k]       + bet[k];
    g_XN[n * 384 + 128 + k] = d1 * rs * gam[128 + k] + bet[128 + k];
    g_XN[n * 384 + 256 + k] = d2 * rs * gam[256 + k] + bet[256 + k];
}

// ---------------- final ----------------
__global__ void k_final(const float* __restrict__ w, const float* __restrict__ b,
                        float* __restrict__ y) {
    int gi = blockIdx.x * 256 + threadIdx.x;
    int n = gi >> 5, lane = gi & 31;
    if (n >= NN) return;
    float s = g_G2[n * 64 + lane] * w[lane] + g_G2[n * 64 + 32 + lane] * w[32 + lane];
    #pragma unroll
    for (int o = 16; o; o >>= 1) s += __shfl_xor_sync(0xffffffffu, s, o);
    if (lane == 0) y[n] = s + b[0];
}

// ---------------- launch ----------------
extern "C" void kernel_launch(void* const* d_in, const int* in_sizes, int n_in,
                              void* d_out, int out_size) {
    const int*   z      = (const int*)d_in[0];
    const float* pos    = (const float*)d_in[1];
    const int*   ei     = (const int*)d_in[3];
    const float* emb_w  = (const float*)d_in[4];
    const float* emb2_w = (const float*)d_in[5];
    const float* emb2_b = (const float*)d_in[6];
    const float* dp1w   = (const float*)d_in[7];
    const float* dp1b   = (const float*)d_in[8];
    const float* dp2w   = (const float*)d_in[9];
    const float* dp2b   = (const float*)d_in[10];
    const float* dp3w   = (const float*)d_in[11];
    const float* dp3b   = (const float*)d_in[12];
    const float* lt0w   = (const float*)d_in[13];
    const float* lt1w   = (const float*)d_in[14];
    const float* lt2w   = (const float*)d_in[15];
    const float* ls0w   = (const float*)d_in[16];
    const float* ls0b   = (const float*)d_in[17];
    const float* ls1w   = (const float*)d_in[18];
    const float* ls1b   = (const float*)d_in[19];
    const float* ing    = (const float*)d_in[20];
    const float* inb    = (const float*)d_in[21];
    const float* linw   = (const float*)d_in[22];
    const float* linb   = (const float*)d_in[23];
    const float* ong    = (const float*)d_in[24];
    const float* onb    = (const float*)d_in[25];
    const float* ol1w   = (const float*)d_in[26];
    const float* ol1b   = (const float*)d_in[27];
    const float* ol2w   = (const float*)d_in[28];
    const float* ol2b   = (const float*)d_in[29];
    float* y = (float*)d_out;

    cudaFuncSetAttribute(tc_mix, cudaFuncAttributeMaxDynamicSharedMemorySize, TG_SMEM);
    cudaFuncSetAttribute(tg_ls0, cudaFuncAttributeMaxDynamicSharedMemorySize, TG_SMEM);
    cudaFuncSetAttribute(tg_ls1, cudaFuncAttributeMaxDynamicSharedMemorySize, TG_SMEM);
    cudaFuncSetAttribute(tg_lin, cudaFuncAttributeMaxDynamicSharedMemorySize, TG_SMEM);

    k_zero_cnt<<<(NN + 255) / 256, 256>>>();
    k_prep<<<128, 128>>>(emb_w, emb2_w, emb2_b);
    k_count<<<NE / 256, 256>>>(ei, pos);
    k_scan<<<1, 1024>>>();
    k_scatter<<<NE / 256, 256>>>(ei, pos, z);
    k_gather<<<NN, 128>>>(z, dp1w, dp1b, dp2w, dp2b, dp3w, dp3b, ing, inb);
    tg_ls0<<<dim3(NN / 128, 2), 256, TG_SMEM>>>(ls0w, ls0b);
    tg_ls1<<<dim3(NN / 128, 3), 256, TG_SMEM>>>(ls1w, ls1b);
    tc_mix<<<dim3(10 * NN / 128, 1), 256, TG_SMEM>>>(lt0w, lt1w, lt2w);
    k_combine_ln<<<NN, 128>>>(ong, onb);
    tg_lin<<<dim3(NN / 128, 1), 256, TG_SMEM>>>(linw, linb);
    gemm_ol1<<<dim3(NN / 128, 1), 256>>>(ol1w, ol1b);
    k_final<<<NN * 32 / 256, 256>>>(ol2w, ol2b, y);
}

// round 7
// speedup vs baseline: 1.5395x; 1.1292x over previous
#include <cuda_runtime.h>
#include <cuda_bf16.h>
#include <math.h>
#include <stdint.h>

#define NN 16384
#define NE 65536
typedef __nv_bfloat16 bf16;

// ---------------- fp32 scratch ----------------
static __device__ __align__(256) float g_U[128 * 128];
static __device__ __align__(256) float g_V[128 * 128];
static __device__ __align__(256) float g_NR[NN * 384];
static __device__ __align__(256) float g_mix[10][NN * 128];
static __device__ __align__(256) float g_G1[NN * 128];
static __device__ __align__(256) float g_G2[NN * 64];

// ---------------- bf16 hi/lo activations (split at producer) ----------------
static __device__ __align__(256) bf16 g_accH[10 * NN * 128], g_accL[10 * NN * 128];
static __device__ __align__(256) bf16 g_TH[NN * 128],  g_TL[NN * 128];
static __device__ __align__(256) bf16 g_H1H[NN * 256], g_H1L[NN * 256];
static __device__ __align__(256) bf16 g_XNH[NN * 384], g_XNL[NN * 384];

// ---------------- bf16 hi/lo weights (split once per call) ----------------
static __device__ __align__(256) bf16 w_ls0H[256 * 128], w_ls0L[256 * 128];
static __device__ __align__(256) bf16 w_ls1H[384 * 256], w_ls1L[384 * 256];
static __device__ __align__(256) bf16 w_linH[128 * 384], w_linL[128 * 384];
static __device__ __align__(256) bf16 w_ltH[3 * 128 * 128], w_ltL[3 * 128 * 128];

// ---------------- CSR edge compaction ----------------
static __device__ __align__(256) int    g_cnt[NN];
static __device__ __align__(256) int    g_off[NN];
static __device__ __align__(256) int    g_fill[NN];
static __device__ __align__(256) float4 g_erec[NE];
static __device__ __align__(256) int    g_ez[NE];

__device__ __forceinline__ float silu(float x) { return x / (1.f + expf(-x)); }
__device__ __forceinline__ void split1(float v, bf16& h, bf16& l) {
    h = __float2bfloat16(v);
    l = __float2bfloat16(v - __bfloat162float(h));
}

#define RBF_START 0.011108996538242306
#define RBF_BETA  (1.0 / ((0.0625 * (1.0 - RBF_START)) * (0.0625 * (1.0 - RBF_START))))
#define RBF_ALPHA (5.0 / 4.5)
#define PI_OVER_C 0.6981317007977318

// =================== MMA plumbing (baseline PTX) ===================
__device__ __forceinline__ uint32_t smem_u32(const void* p) {
    uint32_t a;
    asm("{ .reg .u64 t; cvta.to.shared.u64 t, %1; cvt.u32.u64 %0, t; }" : "=r"(a) : "l"(p));
    return a;
}
__device__ __forceinline__ void ldm_x4(uint32_t addr, uint32_t* r) {
    asm volatile("ldmatrix.sync.aligned.m8n8.x4.shared.b16 {%0,%1,%2,%3}, [%4];"
                 : "=r"(r[0]), "=r"(r[1]), "=r"(r[2]), "=r"(r[3]) : "r"(addr));
}
__device__ __forceinline__ void ldm_x2(uint32_t addr, uint32_t* r) {
    asm volatile("ldmatrix.sync.aligned.m8n8.x2.shared.b16 {%0,%1}, [%2];"
                 : "=r"(r[0]), "=r"(r[1]) : "r"(addr));
}
__device__ __forceinline__ void mma16816(float* c, const uint32_t* a, const uint32_t* b) {
    asm volatile("mma.sync.aligned.m16n8k16.row.col.f32.bf16.bf16.f32 "
                 "{%0,%1,%2,%3}, {%4,%5,%6,%7}, {%8,%9}, {%0,%1,%2,%3};"
                 : "+f"(c[0]), "+f"(c[1]), "+f"(c[2]), "+f"(c[3])
                 : "r"(a[0]), "r"(a[1]), "r"(a[2]), "r"(a[3]), "r"(b[0]), "r"(b[1]));
}
__device__ __forceinline__ void cpa16(uint32_t s, const void* g) {
    asm volatile("cp.async.cg.shared.global [%0], [%1], 16;" :: "r"(s), "l"(g));
}

// SMEM: A tiles 128 x 136 bf16 (hi+lo), W tiles 64 x 136 (hi+lo) -> 102 KB, 2 CTAs/SM
#define TPAD 136
#define SM_A (128 * TPAD * 2)
#define SM_W (64 * TPAD * 2)
#define TG_SMEM (2 * SM_A + 2 * SM_W)   // 104448

// C[M,F] = A[M,K] @ W[F,K]^T, inputs pre-split bf16 hi/lo, fp32 accum via 3-term MMA.
// OUT=0: fp32 C. OUT=1: bf16 hi/lo CH/CL. 256 thr (8 warps: 4m x 2n), BM=128, BN=64.
template <int OUT>
__device__ __forceinline__ void mma_gemm_bf(
    const bf16* __restrict__ AH, const bf16* __restrict__ AL,
    const bf16* __restrict__ WH, const bf16* __restrict__ WL,
    const float* __restrict__ bias,
    float* __restrict__ C, bf16* __restrict__ CH, bf16* __restrict__ CL,
    int K, int F, bool act) {
    extern __shared__ __align__(16) char smem[];
    bf16* saH = (bf16*)smem;
    bf16* saL = (bf16*)(smem + SM_A);
    bf16* swH = (bf16*)(smem + 2 * SM_A);
    bf16* swL = (bf16*)(smem + 2 * SM_A + SM_W);
    const uint32_t aH_u = smem_u32(saH), aL_u = smem_u32(saL);
    const uint32_t wH_u = smem_u32(swH), wL_u = smem_u32(swL);

    const int tid = threadIdx.x, lane = tid & 31, wid = tid >> 5;
    const int wm = wid & 3, wn = wid >> 2;
    const int m0 = blockIdx.x << 7, f0 = blockIdx.y << 6;

    float c[2][4][4];
    #pragma unroll
    for (int i = 0; i < 2; i++)
        #pragma unroll
        for (int j = 0; j < 4; j++)
            #pragma unroll
            for (int q = 0; q < 4; q++) c[i][j][q] = 0.f;

    const int a_row = wm * 32 + (lane & 15);
    const int a_col = (lane >> 4) << 3;
    const int b_row = wn * 32 + (lane & 7);
    const int b_col = ((lane >> 3) & 1) << 3;

    for (int kc = 0; kc < K; kc += 128) {
        __syncthreads();
        // A: 128 rows x 16 chunks(16B); W: 64 rows x 16 chunks — pure cp.async copies
        #pragma unroll
        for (int i = tid; i < 2048; i += 256) {
            int r = i >> 4, c8 = (i & 15) << 3;
            uint32_t so = (uint32_t)(r * TPAD + c8) * 2;
            size_t go = (size_t)(m0 + r) * K + kc + c8;
            cpa16(aH_u + so, AH + go);
            cpa16(aL_u + so, AL + go);
        }
        #pragma unroll
        for (int i = tid; i < 1024; i += 256) {
            int r = i >> 4, c8 = (i & 15) << 3;
            uint32_t so = (uint32_t)(r * TPAD + c8) * 2;
            size_t go = (size_t)(f0 + r) * K + kc + c8;
            cpa16(wH_u + so, WH + go);
            cpa16(wL_u + so, WL + go);
        }
        asm volatile("cp.async.commit_group;");
        asm volatile("cp.async.wait_group 0;" ::: "memory");
        __syncthreads();

        #pragma unroll
        for (int ks = 0; ks < 8; ks++) {
            uint32_t ah[2][4], al[2][4];
            #pragma unroll
            for (int mf = 0; mf < 2; mf++) {
                uint32_t off = (uint32_t)((a_row + mf * 16) * TPAD + a_col + ks * 16) * 2;
                ldm_x4(aH_u + off, ah[mf]);
                ldm_x4(aL_u + off, al[mf]);
            }
            #pragma unroll
            for (int nf = 0; nf < 4; nf++) {
                uint32_t boff = (uint32_t)((b_row + nf * 8) * TPAD + b_col + ks * 16) * 2;
                uint32_t bh[2], bl[2];
                ldm_x2(wH_u + boff, bh);
                ldm_x2(wL_u + boff, bl);
                #pragma unroll
                for (int mf = 0; mf < 2; mf++) {
                    mma16816(c[mf][nf], ah[mf], bh);
                    mma16816(c[mf][nf], ah[mf], bl);
                    mma16816(c[mf][nf], al[mf], bh);
                }
            }
        }
    }

    #pragma unroll
    for (int mf = 0; mf < 2; mf++) {
        #pragma unroll
        for (int nf = 0; nf < 4; nf++) {
            int grow = m0 + wm * 32 + mf * 16 + (lane >> 2);
            int gcol = f0 + wn * 32 + nf * 8 + ((lane & 3) << 1);
            float b0 = bias ? bias[gcol] : 0.f;
            float b1 = bias ? bias[gcol + 1] : 0.f;
            float v0 = c[mf][nf][0] + b0, v1 = c[mf][nf][1] + b1;
            float v2 = c[mf][nf][2] + b0, v3 = c[mf][nf][3] + b1;
            if (act) { v0 = silu(v0); v1 = silu(v1); v2 = silu(v2); v3 = silu(v3); }
            if (OUT == 0) {
                *(float2*)&C[(size_t)grow * F + gcol] = make_float2(v0, v1);
                *(float2*)&C[(size_t)(grow + 8) * F + gcol] = make_float2(v2, v3);
            } else {
                bf16 h0, l0, h1, l1;
                split1(v0, h0, l0); split1(v1, h1, l1);
                *(__nv_bfloat162*)&CH[(size_t)grow * F + gcol] = __halves2bfloat162(h0, h1);
                *(__nv_bfloat162*)&CL[(size_t)grow * F + gcol] = __halves2bfloat162(l0, l1);
                split1(v2, h0, l0); split1(v3, h1, l1);
                *(__nv_bfloat162*)&CH[(size_t)(grow + 8) * F + gcol] = __halves2bfloat162(h0, h1);
                *(__nv_bfloat162*)&CL[(size_t)(grow + 8) * F + gcol] = __halves2bfloat162(l0, l1);
            }
        }
    }
}

__global__ __launch_bounds__(256, 2)
void tg_ls0(const float* __restrict__ b) {
    mma_gemm_bf<1>(g_TH, g_TL, w_ls0H, w_ls0L, b, nullptr, g_H1H, g_H1L, 128, 256, true);
}
__global__ __launch_bounds__(256, 2)
void tg_ls1(const float* __restrict__ b) {
    mma_gemm_bf<0>(g_H1H, g_H1L, w_ls1H, w_ls1L, b, g_NR, nullptr, nullptr, 256, 384, true);
}
__global__ __launch_bounds__(256, 2)
void tg_lin(const float* __restrict__ b) {
    mma_gemm_bf<0>(g_XNH, g_XNL, w_linH, w_linL, b, g_G1, nullptr, nullptr, 384, 128, true);
}
__global__ __launch_bounds__(256, 2)
void tc_mix() {
    int plane = blockIdx.x >> 7;
    int sel = (plane == 0) ? 0 : (plane < 4 ? 1 : 2);
    mma_gemm_bf<0>(g_accH, g_accL, w_ltH + sel * 16384, w_ltL + sel * 16384, nullptr,
                   &g_mix[0][0], nullptr, nullptr, 128, 128, false);
}

// ---------------- weight pre-split ----------------
__global__ void k_wprep(const float* __restrict__ ls0w, const float* __restrict__ ls1w,
                        const float* __restrict__ linw, const float* __restrict__ lt0w,
                        const float* __restrict__ lt1w, const float* __restrict__ lt2w) {
    int j = blockIdx.x * 256 + threadIdx.x;
    const float* src; bf16 *dh, *dl;
    if (j < 32768) { src = ls0w; dh = w_ls0H; dl = w_ls0L; }
    else if ((j -= 32768) < 98304) { src = ls1w; dh = w_ls1H; dl = w_ls1L; }
    else if ((j -= 98304) < 49152) { src = linw; dh = w_linH; dl = w_linL; }
    else if ((j -= 49152) < 16384) { src = lt0w; dh = w_ltH; dl = w_ltL; }
    else if ((j -= 16384) < 16384) { src = lt1w; dh = w_ltH + 16384; dl = w_ltL + 16384; }
    else if ((j -= 16384) < 16384) { src = lt2w; dh = w_ltH + 32768; dl = w_ltL + 32768; }
    else return;
    bf16 h, l;
    split1(src[j], h, l);
    dh[j] = h; dl[j] = l;
}

// ---------------- U/V lookup tables ----------------
__global__ void k_prep(const float* __restrict__ emb_w,
                       const float* __restrict__ emb2_w,
                       const float* __restrict__ emb2_b) {
    int zt = blockIdx.x;
    int h  = threadIdx.x;
    float u = emb2_b[h];
    float v = 0.f;
    #pragma unroll 4
    for (int k = 0; k < 128; k++) {
        float e = emb_w[zt * 128 + k];
        u = fmaf(e, emb2_w[h * 256 + k], u);
        v = fmaf(e, emb2_w[h * 256 + 128 + k], v);
    }
    g_U[zt * 128 + h] = u;
    g_V[zt * 128 + h] = v;
}

// =================== CSR edge compaction ===================
__global__ void k_zero_cnt() {
    int i = blockIdx.x * 256 + threadIdx.x;
    if (i < NN) { g_cnt[i] = 0; g_fill[i] = 0; }
}

__global__ void k_count(const int* __restrict__ ei, const float* __restrict__ pos) {
    int e = blockIdx.x * 256 + threadIdx.x;
    if (e >= NE) return;
    int src = ei[e], dst = ei[NE + e];
    float vx = pos[src * 3 + 0] - pos[dst * 3 + 0];
    float vy = pos[src * 3 + 1] - pos[dst * 3 + 1];
    float vz = pos[src * 3 + 2] - pos[dst * 3 + 2];
    float d = sqrtf(vx * vx + vy * vy + vz * vz);
    if (src == dst || d < 4.5f) atomicAdd(&g_cnt[src], 1);
}

__global__ void k_scan() {
    __shared__ int ps[1024];
    int t = threadIdx.x;
    int base = t * 16;
    int4 v0 = *(int4*)&g_cnt[base];
    int4 v1 = *(int4*)&g_cnt[base + 4];
    int4 v2 = *(int4*)&g_cnt[base + 8];
    int4 v3 = *(int4*)&g_cnt[base + 12];
    int cv[16] = {v0.x, v0.y, v0.z, v0.w, v1.x, v1.y, v1.z, v1.w,
                  v2.x, v2.y, v2.z, v2.w, v3.x, v3.y, v3.z, v3.w};
    int local[16];
    int s = 0;
    #pragma unroll
    for (int i = 0; i < 16; i++) { local[i] = s; s += cv[i]; }
    ps[t] = s;
    __syncthreads();
    #pragma unroll
    for (int off = 1; off < 1024; off <<= 1) {
        int v = (t >= off) ? ps[t - off] : 0;
        __syncthreads();
        ps[t] += v;
        __syncthreads();
    }
    int pre = (t == 0) ? 0 : ps[t - 1];
    int4 o0 = make_int4(pre + local[0], pre + local[1], pre + local[2], pre + local[3]);
    int4 o1 = make_int4(pre + local[4], pre + local[5], pre + local[6], pre + local[7]);
    int4 o2 = make_int4(pre + local[8], pre + local[9], pre + local[10], pre + local[11]);
    int4 o3 = make_int4(pre + local[12], pre + local[13], pre + local[14], pre + local[15]);
    *(int4*)&g_off[base] = o0;
    *(int4*)&g_off[base + 4] = o1;
    *(int4*)&g_off[base + 8] = o2;
    *(int4*)&g_off[base + 12] = o3;
}

__global__ void k_scatter(const int* __restrict__ ei, const float* __restrict__ pos,
                          const int* __restrict__ z) {
    int e = blockIdx.x * 256 + threadIdx.x;
    if (e >= NE) return;
    int src = ei[e], dst = ei[NE + e];
    float vx = pos[src * 3 + 0] - pos[dst * 3 + 0];
    float vy = pos[src * 3 + 1] - pos[dst * 3 + 1];
    float vz = pos[src * 3 + 2] - pos[dst * 3 + 2];
    float d = sqrtf(vx * vx + vy * vy + vz * vz);
    bool selfe = (src == dst);
    if (!selfe && !(d < 4.5f)) return;
    int slot = g_off[src] + atomicAdd(&g_fill[src], 1);
    g_erec[slot] = make_float4(vx, vy, vz, d);
    g_ez[slot] = z[dst] | (selfe ? (int)0x80000000 : 0);
}

// =================== gather + tensor-norm + layernorm(128), fused ===================
__global__ void k_gather(const int* __restrict__ z,
                         const float* __restrict__ dp1w, const float* __restrict__ dp1b,
                         const float* __restrict__ dp2w, const float* __restrict__ dp2b,
                         const float* __restrict__ dp3w, const float* __restrict__ dp3b,
                         const float* __restrict__ gam, const float* __restrict__ bet) {
    int n = blockIdx.x, h = threadIdx.x;
    __shared__ __align__(16) float s_attr[32];
    __shared__ float red[4];

    int cnt = g_cnt[n];
    int off = g_off[n];
    int zn = z[n];
    float Un = g_U[(zn << 7) + h];
    float b1h = dp1b[h], b2h = dp2b[h], b3h = dp3b[h];

    float a = 0.f, bx = 0.f, by = 0.f, bz = 0.f;
    float xx = 0.f, yy = 0.f, zz = 0.f, xy = 0.f, xz = 0.f, yz = 0.f;

    for (int j = 0; j < cnt; j++) {
        float4 rec = g_erec[off + j];
        int ezd = g_ez[off + j];
        bool selfe = (ezd < 0);
        int zdst = ezd & 127;
        float d = rec.w;
        float cut = 0.5f * (cosf(d * (float)PI_OVER_C) + 1.0f);
        float inv = selfe ? 1.0f : (1.0f / d);
        float vx = rec.x * inv, vy = rec.y * inv, vz = rec.z * inv;

        __syncthreads();
        if (h < 32) {
            float mean = (float)RBF_START + (float)h * (float)((1.0 - RBF_START) / 31.0);
            float g = expf(-(float)RBF_ALPHA * d);
            float diff = g - mean;
            s_attr[h] = cut * expf(-(float)RBF_BETA * diff * diff);
        }
        __syncthreads();

        float C = cut * (Un + g_V[(zdst << 7) + h]);
        float d1 = b1h, d2 = b2h, d3 = b3h;
        #pragma unroll
        for (int r = 0; r < 32; r += 4) {
            float4 a4 = *(const float4*)&s_attr[r];
            float4 w1 = *(const float4*)&dp1w[h * 32 + r];
            float4 w2 = *(const float4*)&dp2w[h * 32 + r];
            float4 w3 = *(const float4*)&dp3w[h * 32 + r];
            d1 += a4.x * w1.x + a4.y * w1.y + a4.z * w1.z + a4.w * w1.w;
            d2 += a4.x * w2.x + a4.y * w2.y + a4.z * w2.z + a4.w * w2.w;
            d3 += a4.x * w3.x + a4.y * w3.y + a4.z * w3.z + a4.w * w3.w;
        }
        float ai = d1 * C, cb = d2 * C, cs = d3 * C;
        a  += ai;
        bx += cb * vx; by += cb * vy; bz += cb * vz;
        xx += cs * vx * vx; yy += cs * vy * vy; zz += cs * vz * vz;
        xy += cs * vx * vy; xz += cs * vx * vz; yz += cs * vy * vz;
    }

    int i = (n << 7) + h;
    float vals[10] = {a, bx, by, bz, xx, yy, zz, xy, xz, yz};
    #pragma unroll
    for (int p = 0; p < 10; p++) {
        bf16 hh, ll;
        split1(vals[p], hh, ll);
        g_accH[(size_t)p * (NN * 128) + i] = hh;
        g_accL[(size_t)p * (NN * 128) + i] = ll;
    }

    float tr = xx + yy + zz;
    float ms = xx * xx + yy * yy + zz * zz + 2.f * (xy * xy + xz * xz + yz * yz);
    float tn = 3.f * a * a + 2.f * (bx * bx + by * by + bz * bz) + ms - tr * tr * (1.f / 3.f);

    float v = tn;
    #pragma unroll
    for (int o = 16; o; o >>= 1) v += __shfl_xor_sync(0xffffffffu, v, o);
    __syncthreads();
    if ((h & 31) == 0) red[h >> 5] = v;
    __syncthreads();
    float mean = (red[0] + red[1] + red[2] + red[3]) * (1.f / 128.f);
    float dev = tn - mean;
    v = dev * dev;
    #pragma unroll
    for (int o = 16; o; o >>= 1) v += __shfl_xor_sync(0xffffffffu, v, o);
    __syncthreads();
    if ((h & 31) == 0) red[h >> 5] = v;
    __syncthreads();
    float var = (red[0] + red[1] + red[2] + red[3]) * (1.f / 128.f);
    float T = dev * rsqrtf(var + 1e-5f) * gam[h] + bet[h];
    bf16 th, tl;
    split1(T, th, tl);
    g_TH[i] = th; g_TL[i] = tl;
}

// ---------------- SIMT SGEMM (ol1 only: F=64) ----------------
__device__ __forceinline__ void sgemm_body(const float* __restrict__ A,
                                           const float* __restrict__ W,
                                           const float* __restrict__ bias,
                                           float* __restrict__ C,
                                           int K, int F, bool act) {
    __shared__ __align__(16) float As[8][128];
    __shared__ __align__(16) float Ws[8][64];
    const int tid = threadIdx.x;
    const int tx = tid & 15, ty = tid >> 4;
    const int m0 = blockIdx.x << 7;
    const int f0 = blockIdx.y << 6;
    float acc[8][4];
    #pragma unroll
    for (int i = 0; i < 8; i++)
        #pragma unroll
        for (int j = 0; j < 4; j++) acc[i][j] = 0.f;

    const int arow = tid >> 1, acol = (tid & 1) << 2;
    const int wrow = (tid & 127) >> 1, wcol = acol;
    const float* Ag = A + (size_t)(m0 + arow) * K + acol;
    const float* Wg = W + (size_t)(f0 + wrow) * K + wcol;

    for (int k0 = 0; k0 < K; k0 += 8) {
        float4 av = *(const float4*)(Ag + k0);
        As[acol + 0][arow] = av.x; As[acol + 1][arow] = av.y;
        As[acol + 2][arow] = av.z; As[acol + 3][arow] = av.w;
        if (tid < 128) {
            float4 wv = *(const float4*)(Wg + k0);
            Ws[wcol + 0][wrow] = wv.x; Ws[wcol + 1][wrow] = wv.y;
            Ws[wcol + 2][wrow] = wv.z; Ws[wcol + 3][wrow] = wv.w;
        }
        __syncthreads();
        #pragma unroll
        for (int k = 0; k < 8; k++) {
            float4 a0 = *(const float4*)&As[k][ty << 3];
            float4 a1 = *(const float4*)&As[k][(ty << 3) + 4];
            float4 wv = *(const float4*)&Ws[k][tx << 2];
            float am[8] = {a0.x, a0.y, a0.z, a0.w, a1.x, a1.y, a1.z, a1.w};
            float wn[4] = {wv.x, wv.y, wv.z, wv.w};
            #pragma unroll
            for (int i = 0; i < 8; i++)
                #pragma unroll
                for (int j = 0; j < 4; j++)
                    acc[i][j] = fmaf(am[i], wn[j], acc[i][j]);
        }
        __syncthreads();
    }

    float bj[4];
    #pragma unroll
    for (int j = 0; j < 4; j++) bj[j] = bias ? bias[f0 + (tx << 2) + j] : 0.f;
    #pragma unroll
    for (int i = 0; i < 8; i++) {
        float v0 = acc[i][0] + bj[0];
        float v1 = acc[i][1] + bj[1];
        float v2 = acc[i][2] + bj[2];
        float v3 = acc[i][3] + bj[3];
        if (act) { v0 = silu(v0); v1 = silu(v1); v2 = silu(v2); v3 = silu(v3); }
        *(float4*)&C[(size_t)(m0 + (ty << 3) + i) * F + f0 + (tx << 2)] =
            make_float4(v0, v1, v2, v3);
    }
}

__global__ void gemm_ol1(const float* W, const float* b) { sgemm_body(g_G1, W, b, g_G2, 128, 64, true); }

// ---------------- combine + layernorm(384), fused ----------------
__global__ void k_combine_ln(const float* __restrict__ gam, const float* __restrict__ bet) {
    int n = blockIdx.x, k = threadIdx.x;
    int idx = (n << 7) + k;
    float Ip = g_mix[0][idx];
    float B0 = g_mix[1][idx], B1 = g_mix[2][idx], B2 = g_mix[3][idx];
    float xx = g_mix[4][idx], yy = g_mix[5][idx], zz = g_mix[6][idx];
    float xy = g_mix[7][idx], xz = g_mix[8][idx], yz = g_mix[9][idx];
    const float* nr = &g_NR[n * 384 + 3 * k];
    float n0 = nr[0], n1 = nr[1], n2 = nr[2];
    float t  = Ip * n0;
    float x0 = 3.f * t * t;
    float bb = B0 * B0 + B1 * B1 + B2 * B2;
    float x1 = 2.f * bb * n1 * n1;
    float tr = xx + yy + zz;
    float ms = xx * xx + yy * yy + zz * zz + 2.f * (xy * xy + xz * xz + yz * yz);
    float x2 = (ms - tr * tr * (1.f / 3.f)) * n2 * n2;

    __shared__ float red[4];
    float v = x0 + x1 + x2;
    #pragma unroll
    for (int o = 16; o; o >>= 1) v += __shfl_xor_sync(0xffffffffu, v, o);
    if ((k & 31) == 0) red[k >> 5] = v;
    __syncthreads();
    float mean = (red[0] + red[1] + red[2] + red[3]) * (1.f / 384.f);
    __syncthreads();
    float d0 = x0 - mean, d1 = x1 - mean, d2 = x2 - mean;
    v = d0 * d0 + d1 * d1 + d2 * d2;
    #pragma unroll
    for (int o = 16; o; o >>= 1) v += __shfl_xor_sync(0xffffffffu, v, o);
    if ((k & 31) == 0) red[k >> 5] = v;
    __syncthreads();
    float var = (red[0] + red[1] + red[2] + red[3]) * (1.f / 384.f);
    float rs = rsqrtf(var + 1e-5f);
    float o0 = d0 * rs * gam[k]       + bet[k];
    float o1 = d1 * rs * gam[128 + k] + bet[128 + k];
    float o2 = d2 * rs * gam[256 + k] + bet[256 + k];
    bf16 hh, ll;
    split1(o0, hh, ll); g_XNH[n * 384 + k]       = hh; g_XNL[n * 384 + k]       = ll;
    split1(o1, hh, ll); g_XNH[n * 384 + 128 + k] = hh; g_XNL[n * 384 + 128 + k] = ll;
    split1(o2, hh, ll); g_XNH[n * 384 + 256 + k] = hh; g_XNL[n * 384 + 256 + k] = ll;
}

// ---------------- final ----------------
__global__ void k_final(const float* __restrict__ w, const float* __restrict__ b,
                        float* __restrict__ y) {
    int gi = blockIdx.x * 256 + threadIdx.x;
    int n = gi >> 5, lane = gi & 31;
    if (n >= NN) return;
    float s = g_G2[n * 64 + lane] * w[lane] + g_G2[n * 64 + 32 + lane] * w[32 + lane];
    #pragma unroll
    for (int o = 16; o; o >>= 1) s += __shfl_xor_sync(0xffffffffu, s, o);
    if (lane == 0) y[n] = s + b[0];
}

// ---------------- launch ----------------
extern "C" void kernel_launch(void* const* d_in, const int* in_sizes, int n_in,
                              void* d_out, int out_size) {
    const int*   z      = (const int*)d_in[0];
    const float* pos    = (const float*)d_in[1];
    const int*   ei     = (const int*)d_in[3];
    const float* emb_w  = (const float*)d_in[4];
    const float* emb2_w = (const float*)d_in[5];
    const float* emb2_b = (const float*)d_in[6];
    const float* dp1w   = (const float*)d_in[7];
    const float* dp1b   = (const float*)d_in[8];
    const float* dp2w   = (const float*)d_in[9];
    const float* dp2b   = (const float*)d_in[10];
    const float* dp3w   = (const float*)d_in[11];
    const float* dp3b   = (const float*)d_in[12];
    const float* lt0w   = (const float*)d_in[13];
    const float* lt1w   = (const float*)d_in[14];
    const float* lt2w   = (const float*)d_in[15];
    const float* ls0w   = (const float*)d_in[16];
    const float* ls0b   = (const float*)d_in[17];
    const float* ls1w   = (const float*)d_in[18];
    const float* ls1b   = (const float*)d_in[19];
    const float* ing    = (const float*)d_in[20];
    const float* inb    = (const float*)d_in[21];
    const float* linw   = (const float*)d_in[22];
    const float* linb   = (const float*)d_in[23];
    const float* ong    = (const float*)d_in[24];
    const float* onb    = (const float*)d_in[25];
    const float* ol1w   = (const float*)d_in[26];
    const float* ol1b   = (const float*)d_in[27];
    const float* ol2w   = (const float*)d_in[28];
    const float* ol2b   = (const float*)d_in[29];
    float* y = (float*)d_out;

    cudaFuncSetAttribute(tc_mix, cudaFuncAttributeMaxDynamicSharedMemorySize, TG_SMEM);
    cudaFuncSetAttribute(tg_ls0, cudaFuncAttributeMaxDynamicSharedMemorySize, TG_SMEM);
    cudaFuncSetAttribute(tg_ls1, cudaFuncAttributeMaxDynamicSharedMemorySize, TG_SMEM);
    cudaFuncSetAttribute(tg_lin, cudaFuncAttributeMaxDynamicSharedMemorySize, TG_SMEM);

    k_zero_cnt<<<(NN + 255) / 256, 256>>>();
    k_prep<<<128, 128>>>(emb_w, emb2_w, emb2_b);
    k_wprep<<<896, 256>>>(ls0w, ls1w, linw, lt0w, lt1w, lt2w);
    k_count<<<NE / 256, 256>>>(ei, pos);
    k_scan<<<1, 1024>>>();
    k_scatter<<<NE / 256, 256>>>(ei, pos, z);
    k_gather<<<NN, 128>>>(z, dp1w, dp1b, dp2w, dp2b, dp3w, dp3b, ing, inb);
    tg_ls0<<<dim3(NN / 128, 4), 256, TG_SMEM>>>(ls0b);
    tg_ls1<<<dim3(NN / 128, 6), 256, TG_SMEM>>>(ls1b);
    tc_mix<<<dim3(10 * NN / 128, 2), 256, TG_SMEM>>>();
    k_combine_ln<<<NN, 128>>>(ong, onb);
    tg_lin<<<dim3(NN / 128, 2), 256, TG_SMEM>>>(linb);
    gemm_ol1<<<dim3(NN / 128, 1), 256>>>(ol1w, ol1b);
    k_final<<<NN * 32 / 256, 256>>>(ol2w, ol2b, y);
}